// round 3
// baseline (speedup 1.0000x reference)
#include <cuda_runtime.h>
#include <cuda_bf16.h>

#define FULL 0xffffffffu
#define L2E  1.4426950408889634f
#define LN2  0.6931471805599453f
#define CRF_S 1024
#define CRF_T 16

static __device__ __forceinline__ float ex2f_(float x){ float y; asm("ex2.approx.ftz.f32 %0,%1;" :"=f"(y):"f"(x)); return y; }
static __device__ __forceinline__ float lg2f_(float x){ float y; asm("lg2.approx.ftz.f32 %0,%1;" :"=f"(y):"f"(x)); return y; }

static __device__ __forceinline__ unsigned dup_lo(unsigned u){ unsigned r; asm("prmt.b32 %0,%1,%1,0x1010;" : "=r"(r):"r"(u)); return r; }
static __device__ __forceinline__ unsigned dup_hi(unsigned u){ unsigned r; asm("prmt.b32 %0,%1,%1,0x3232;" : "=r"(r):"r"(u)); return r; }

union UBF { unsigned u; __nv_bfloat162 b; float f; };
static __device__ __forceinline__ unsigned bf2u(__nv_bfloat162 v){ UBF c; c.b = v; return c.u; }
static __device__ __forceinline__ __nv_bfloat162 u2bf(unsigned u){ UBF c; c.u = u; return c.b; }
static __device__ __forceinline__ float bflo_f(unsigned u){ UBF c; c.u = u << 16; return c.f; }
static __device__ __forceinline__ float bfhi_f(unsigned u){ UBF c; c.u = u & 0xffff0000u; return c.f; }

__device__ float g_nll[1024];

// ---- one CRF step: r_c = sum_i q_i * E[i][c], both columns packed in bf16x2 ----
#define STEP_CORE(K) \
    unsigned s0=__shfl_sync(FULL,pku, 0,16), s1=__shfl_sync(FULL,pku, 2,16), \
             s2=__shfl_sync(FULL,pku, 4,16), s3=__shfl_sync(FULL,pku, 6,16), \
             s4=__shfl_sync(FULL,pku, 8,16), s5=__shfl_sync(FULL,pku,10,16), \
             s6=__shfl_sync(FULL,pku,12,16), s7=__shfl_sync(FULL,pku,14,16); \
    __nv_bfloat162 A_ = __hmul2(u2bf(dup_lo(s0)), Ep[0]); \
    __nv_bfloat162 B_ = __hmul2(u2bf(dup_hi(s0)), Ep[1]); \
    __nv_bfloat162 C_ = __hmul2(u2bf(dup_lo(s1)), Ep[2]); \
    __nv_bfloat162 D_ = __hmul2(u2bf(dup_hi(s1)), Ep[3]); \
    A_ = __hfma2(u2bf(dup_lo(s2)), Ep[ 4], A_); \
    B_ = __hfma2(u2bf(dup_hi(s2)), Ep[ 5], B_); \
    C_ = __hfma2(u2bf(dup_lo(s3)), Ep[ 6], C_); \
    D_ = __hfma2(u2bf(dup_hi(s3)), Ep[ 7], D_); \
    A_ = __hfma2(u2bf(dup_lo(s4)), Ep[ 8], A_); \
    B_ = __hfma2(u2bf(dup_hi(s4)), Ep[ 9], B_); \
    C_ = __hfma2(u2bf(dup_lo(s5)), Ep[10], C_); \
    D_ = __hfma2(u2bf(dup_hi(s5)), Ep[11], D_); \
    A_ = __hfma2(u2bf(dup_lo(s6)), Ep[12], A_); \
    B_ = __hfma2(u2bf(dup_hi(s6)), Ep[13], B_); \
    C_ = __hfma2(u2bf(dup_lo(s7)), Ep[14], C_); \
    D_ = __hfma2(u2bf(dup_hi(s7)), Ep[15], D_); \
    A_ = __hadd2(A_, B_); C_ = __hadd2(C_, D_); A_ = __hadd2(A_, C_); \
    __nv_bfloat162 pnew = __hmul2(A_, gpk_c[(K)]);

#define RENORM do { \
    unsigned u0_ = __shfl_sync(FULL, pku, 0, 16); \
    float l_  = rintf(lg2f_(bflo_f(u0_))); \
    float sc_ = ex2f_(-l_); \
    pku  = bf2u(__hmul2(u2bf(pku), __floats2bfloat162_rn(sc_, sc_))); \
    off2 += l_; \
} while (0)

#define STEP_F(K) do { STEP_CORE(K); pku = bf2u(pnew); if (((K)&7)==7) RENORM; } while (0)
#define STEP_S(K) do { STEP_CORE(K); \
    int mk_ = __shfl_sync(FULL, msk_c, (K), 16); \
    if (mk_) pku = bf2u(pnew); \
    if (((K)&7)==7) RENORM; } while (0)

__global__ void __launch_bounds__(32, 1)
crf_forward_kernel(const float* __restrict__ em,
                   const int* __restrict__ tags,
                   const int* __restrict__ mask,
                   const float* __restrict__ trans,
                   const float* __restrict__ start_t,
                   const float* __restrict__ end_t)
{
    __shared__ float s_trans[256];
    __shared__ float s_start[16];
    int tid = threadIdx.x;
    for (int i = tid; i < 256; i += 32) s_trans[i] = trans[i];
    if (tid < 16) s_start[tid] = start_t[tid];
    __syncwarp();

    const int j   = tid & 15;          // lane within 16-lane group
    const int grp = tid >> 4;          // 0 / 1
    const int b   = blockIdx.x * 2 + grp;
    const int c0  = j & 14;            // this lane's column pair (c0, c0+1)

    const float* emb = em   + (size_t)b * CRF_S * CRF_T;
    const int*   tp  = tags + (size_t)b * CRF_S;
    const int*   mp  = mask + (size_t)b * CRF_S;

    // Ep[i] = bf16x2( exp(trans[i][c0]), exp(trans[i][c0+1]) )
    __nv_bfloat162 Ep[16];
    #pragma unroll
    for (int i = 0; i < 16; i++) {
        float ea = ex2f_(__ldg(trans + i*16 + c0    ) * L2E);
        float eb = ex2f_(__ldg(trans + i*16 + c0 + 1) * L2E);
        Ep[i] = __floats2bfloat162_rn(ea, eb);
    }
    const float eendA = ex2f_(__ldg(end_t + c0    ) * L2E);
    const float eendB = ex2f_(__ldg(end_t + c0 + 1) * L2E);

    // prefetch block 0
    float2 em_n[16];
    #pragma unroll
    for (int u = 0; u < 16; u++) em_n[u] = __ldg((const float2*)(emb + u*16 + c0));
    int tag_n = __ldg(tp + j);
    int msk_n = __ldg(mp + j);

    float2 em_c[16];
    __nv_bfloat162 gpk_c[16];
    int tag_c, msk_c;

    unsigned pku = 0;
    float off2 = 0.0f, gold = 0.0f;
    int carry_tag = 0, packlm = -2147483647;

    for (int nb = 0; nb < 64; nb++) {
        const int t0 = nb * 16;
        #pragma unroll
        for (int u = 0; u < 16; u++) em_c[u] = em_n[u];
        tag_c = tag_n; msk_c = msk_n;

        if (nb < 63) {
            const int tn = t0 + 16;
            #pragma unroll
            for (int u = 0; u < 16; u++) em_n[u] = __ldg((const float2*)(emb + (tn+u)*16 + c0));
            tag_n = __ldg(tp + tn + j);
            msk_n = __ldg(mp + tn + j);
        }

        // per-step growth factors for this block (off critical path)
        #pragma unroll
        for (int u = 0; u < 16; u++)
            gpk_c[u] = __floats2bfloat162_rn(ex2f_(em_c[u].x * L2E), ex2f_(em_c[u].y * L2E));

        // ---- gold path: lane-local, one timestep per lane ----
        {
            const int t  = t0 + j;
            const int tg = tag_c;
            int tgp = __shfl_up_sync(FULL, tag_c, 1, 16);
            const int l15 = __shfl_sync(FULL, tag_c, 15, 16);
            if (j == 0) tgp = carry_tag;
            carry_tag = l15;
            const float emg = __ldg(emb + t*16 + tg);
            if (t == 0) {
                gold += s_start[tg] + emg;                       // ungated, matches ref
                if (msk_c) packlm = tg;                          // (0<<4)|tg
            } else if (msk_c) {
                gold += emg + s_trans[tg*16 + tgp];
                packlm = (t << 4) | tg;
            }
        }

        const unsigned bal = __ballot_sync(FULL, msk_c != 0);

        if (nb == 0) {
            // init: score0 = start + em[0] (log2 domain, normalized to state 0)
            float sA = (s_start[c0    ] + em_c[0].x) * L2E;
            float sB = (s_start[c0 + 1] + em_c[0].y) * L2E;
            float m0 = __shfl_sync(FULL, sA, 0, 16);
            pku  = bf2u(__floats2bfloat162_rn(ex2f_(sA - m0), ex2f_(sB - m0)));
            off2 = m0;

            if (bal == FULL) {
                STEP_F(1);  STEP_F(2);  STEP_F(3);  STEP_F(4);  STEP_F(5);
                STEP_F(6);  STEP_F(7);  STEP_F(8);  STEP_F(9);  STEP_F(10);
                STEP_F(11); STEP_F(12); STEP_F(13); STEP_F(14); STEP_F(15);
            } else {
                STEP_S(1);  STEP_S(2);  STEP_S(3);  STEP_S(4);  STEP_S(5);
                STEP_S(6);  STEP_S(7);  STEP_S(8);  STEP_S(9);  STEP_S(10);
                STEP_S(11); STEP_S(12); STEP_S(13); STEP_S(14); STEP_S(15);
            }
        } else {
            if (bal == FULL) {
                STEP_F(0);  STEP_F(1);  STEP_F(2);  STEP_F(3);
                STEP_F(4);  STEP_F(5);  STEP_F(6);  STEP_F(7);
                STEP_F(8);  STEP_F(9);  STEP_F(10); STEP_F(11);
                STEP_F(12); STEP_F(13); STEP_F(14); STEP_F(15);
            } else {
                STEP_S(0);  STEP_S(1);  STEP_S(2);  STEP_S(3);
                STEP_S(4);  STEP_S(5);  STEP_S(6);  STEP_S(7);
                STEP_S(8);  STEP_S(9);  STEP_S(10); STEP_S(11);
                STEP_S(12); STEP_S(13); STEP_S(14); STEP_S(15);
            }
        }
    }

    // ---- epilogue ----
    float pA = bflo_f(pku), pB = bfhi_f(pku);
    float z  = (j & 1) ? 0.0f : (pA * eendA + pB * eendB);
    z += __shfl_xor_sync(FULL, z, 8, 16);
    z += __shfl_xor_sync(FULL, z, 4, 16);
    z += __shfl_xor_sync(FULL, z, 2, 16);
    z += __shfl_xor_sync(FULL, z, 1, 16);

    gold += __shfl_xor_sync(FULL, gold, 8, 16);
    gold += __shfl_xor_sync(FULL, gold, 4, 16);
    gold += __shfl_xor_sync(FULL, gold, 2, 16);
    gold += __shfl_xor_sync(FULL, gold, 1, 16);

    packlm = max(packlm, __shfl_xor_sync(FULL, packlm, 8, 16));
    packlm = max(packlm, __shfl_xor_sync(FULL, packlm, 4, 16));
    packlm = max(packlm, __shfl_xor_sync(FULL, packlm, 2, 16));
    packlm = max(packlm, __shfl_xor_sync(FULL, packlm, 1, 16));

    if (j == 0) {
        const int ltf = packlm & 15;
        const float logZ = (off2 + lg2f_(z)) * LN2;
        g_nll[b] = logZ - (gold + __ldg(end_t + ltf));
    }
}

__global__ void crf_reduce_kernel(float* __restrict__ out)
{
    __shared__ float sm[256];
    int tid = threadIdx.x;
    float v = g_nll[tid] + g_nll[tid + 256] + g_nll[tid + 512] + g_nll[tid + 768];
    sm[tid] = v;
    __syncthreads();
    #pragma unroll
    for (int s = 128; s > 0; s >>= 1) {
        if (tid < s) sm[tid] += sm[tid + s];
        __syncthreads();
    }
    if (tid == 0) out[0] = sm[0] * (1.0f / 1024.0f);
}

extern "C" void kernel_launch(void* const* d_in, const int* in_sizes, int n_in,
                              void* d_out, int out_size)
{
    const float* emissions = (const float*)d_in[0];
    const int*   tags      = (const int*)d_in[1];
    const int*   mask      = (const int*)d_in[2];
    const float* trans     = (const float*)d_in[3];
    const float* start_t   = (const float*)d_in[4];
    const float* end_t     = (const float*)d_in[5];
    float* out = (float*)d_out;

    crf_forward_kernel<<<512, 32>>>(emissions, tags, mask, trans, start_t, end_t);
    crf_reduce_kernel<<<1, 256>>>(out);
}

// round 5
// speedup vs baseline: 1.3309x; 1.3309x over previous
#include <cuda_runtime.h>
#include <cuda_bf16.h>

#define FULL 0xffffffffu
#define L2E  1.4426950408889634f
#define LN2  0.6931471805599453f
#define CRF_S 1024
#define CRF_T 16
#define ONEBF 0x3F803F80u

static __device__ __forceinline__ float ex2f_(float x){ float y; asm("ex2.approx.ftz.f32 %0,%1;" :"=f"(y):"f"(x)); return y; }
static __device__ __forceinline__ float lg2f_(float x){ float y; asm("lg2.approx.ftz.f32 %0,%1;" :"=f"(y):"f"(x)); return y; }
static __device__ __forceinline__ unsigned dup_lo(unsigned u){ unsigned r; asm("prmt.b32 %0,%1,%1,0x1010;" : "=r"(r):"r"(u)); return r; }
static __device__ __forceinline__ unsigned dup_hi(unsigned u){ unsigned r; asm("prmt.b32 %0,%1,%1,0x3232;" : "=r"(r):"r"(u)); return r; }

union UBF { unsigned u; __nv_bfloat162 b; float f; };
static __device__ __forceinline__ unsigned bf2u(__nv_bfloat162 v){ UBF c; c.b = v; return c.u; }
static __device__ __forceinline__ __nv_bfloat162 u2bf(unsigned u){ UBF c; c.u = u; return c.b; }
static __device__ __forceinline__ float bflo_f(unsigned u){ UBF c; c.u = u << 16; return c.f; }
static __device__ __forceinline__ float bfhi_f(unsigned u){ UBF c; c.u = u & 0xffff0000u; return c.f; }

__device__ float g_nll[1024];

// gather + 16x2 FMA tree: w = sum_i v_i * Ep[i]  (within 16-lane group)
#define GATHER_TREE \
    unsigned s0=__shfl_sync(FULL,v_, 0,16), s1=__shfl_sync(FULL,v_, 2,16), \
             s2=__shfl_sync(FULL,v_, 4,16), s3=__shfl_sync(FULL,v_, 6,16), \
             s4=__shfl_sync(FULL,v_, 8,16), s5=__shfl_sync(FULL,v_,10,16), \
             s6=__shfl_sync(FULL,v_,12,16), s7=__shfl_sync(FULL,v_,14,16); \
    __nv_bfloat162 A_ = __hmul2(u2bf(dup_lo(s0)), Ep[0]); \
    __nv_bfloat162 B_ = __hmul2(u2bf(dup_hi(s0)), Ep[1]); \
    __nv_bfloat162 C_ = __hmul2(u2bf(dup_lo(s1)), Ep[2]); \
    __nv_bfloat162 D_ = __hmul2(u2bf(dup_hi(s1)), Ep[3]); \
    A_ = __hfma2(u2bf(dup_lo(s2)), Ep[ 4], A_); \
    B_ = __hfma2(u2bf(dup_hi(s2)), Ep[ 5], B_); \
    C_ = __hfma2(u2bf(dup_lo(s3)), Ep[ 6], C_); \
    D_ = __hfma2(u2bf(dup_hi(s3)), Ep[ 7], D_); \
    A_ = __hfma2(u2bf(dup_lo(s4)), Ep[ 8], A_); \
    B_ = __hfma2(u2bf(dup_hi(s4)), Ep[ 9], B_); \
    C_ = __hfma2(u2bf(dup_lo(s5)), Ep[10], C_); \
    D_ = __hfma2(u2bf(dup_hi(s5)), Ep[11], D_); \
    A_ = __hfma2(u2bf(dup_lo(s6)), Ep[12], A_); \
    B_ = __hfma2(u2bf(dup_hi(s6)), Ep[13], B_); \
    C_ = __hfma2(u2bf(dup_lo(s7)), Ep[14], C_); \
    D_ = __hfma2(u2bf(dup_hi(s7)), Ep[15], D_); \
    A_ = __hadd2(A_, B_); C_ = __hadd2(C_, D_); A_ = __hadd2(A_, C_);

// integer renorm: scale both chains' pair so lane-0-low ~ 1.0 (power of 2, exact)
#define RENORM do { \
    unsigned u0_ = __shfl_sync(FULL, pku, 0, 16); \
    int Eb_ = (int)((u0_ >> 7) & 0xffu); \
    unsigned h_ = ((unsigned)(254 - Eb_)) << 7; \
    unsigned scl_ = h_ | (h_ << 16); \
    pku  = bf2u(__hmul2(u2bf(pku),  u2bf(scl_))); \
    ptrk = bf2u(__hmul2(u2bf(ptrk), u2bf(scl_))); \
    off2 += (float)(Eb_ - 127); \
} while (0)

#define STEP_F(K) do { \
    unsigned v_ = bf2u(__hmul2(u2bf(pku), u2bf(gpk_c[(K)]))); \
    GATHER_TREE; \
    ptrk = v_; pku = bf2u(A_); \
    if (((K)&7)==7) RENORM; } while (0)

#define STEP_S(K) do { \
    unsigned v_ = bf2u(__hmul2(u2bf(pku), u2bf(gpk_c[(K)]))); \
    int g_ = __shfl_sync(FULL, gate_c, (K), 16); \
    GATHER_TREE; \
    if (g_) { ptrk = v_; pku = bf2u(A_); } \
    if (((K)&7)==7) RENORM; } while (0)

__global__ void __launch_bounds__(32, 1)
crf_forward_kernel(const float* __restrict__ em,
                   const int* __restrict__ tags,
                   const int* __restrict__ mask,
                   const float* __restrict__ trans,
                   const float* __restrict__ start_t,
                   const float* __restrict__ end_t)
{
    __shared__ float s_trans[256];
    __shared__ float s_start[16];
    int tid = threadIdx.x;
    for (int i = tid; i < 256; i += 32) s_trans[i] = trans[i];
    if (tid < 16) s_start[tid] = start_t[tid];
    __syncwarp();

    const int  j     = tid & 15;
    const bool isBwd = (tid >= 16);
    const int  b     = blockIdx.x;
    const int  c0    = j & 14;

    const float* emb = em   + (size_t)b * CRF_S * CRF_T;
    const int*   tp  = tags + (size_t)b * CRF_S;
    const int*   mp  = mask + (size_t)b * CRF_S;

    // per-lane E operand: fwd lane -> E column pair (src i -> dest c0,c0+1)
    //                     bwd lane -> E row pair    (E[c0][i], E[c0+1][i])
    __nv_bfloat162 Ep[16];
    #pragma unroll
    for (int i = 0; i < 16; i++) {
        int iA = isBwd ? (c0*16 + i)     : (i*16 + c0);
        int iB = isBwd ? ((c0+1)*16 + i) : (i*16 + c0 + 1);
        Ep[i] = __floats2bfloat162_rn(ex2f_(__ldg(trans + iA) * L2E),
                                      ex2f_(__ldg(trans + iB) * L2E));
    }

    // direction bases: em/gate stream, gold stream
    const int gateBase = isBwd ? 1023 : 0;
    const int gdir     = isBwd ? -1   : 1;
    const int goldBase = isBwd ? 512  : 0;
    const float* emL   = emb + c0;

    // prefetch block 0
    float2 em_n[16];
    #pragma unroll
    for (int u = 0; u < 16; u++)
        em_n[u] = __ldg((const float2*)(emL + (size_t)(gateBase + gdir*u) * 16));
    int tag_n  = __ldg(tp + goldBase + j);
    int mskg_n = __ldg(mp + goldBase + j);            // gold gate (ascending per half)
    int gate_n = __ldg(mp + gateBase + gdir*j);       // recurrence gate (stream order)

    float2 em_c[16];
    unsigned gpk_c[16];
    int tag_c, mskg_c, gate_c;

    unsigned pku = 0, ptrk = ONEBF;
    float off2 = 0.0f, gold = 0.0f;
    int carry_tag = isBwd ? __ldg(tp + 511) : 0;
    int packlm = -2147483647;

    for (int nb = 0; nb < 32; nb++) {
        const int k0 = nb * 16;
        #pragma unroll
        for (int u = 0; u < 16; u++) em_c[u] = em_n[u];
        tag_c = tag_n; mskg_c = mskg_n; gate_c = gate_n;

        if (nb < 31) {
            const int kn = k0 + 16;
            #pragma unroll
            for (int u = 0; u < 16; u++)
                em_n[u] = __ldg((const float2*)(emL + (size_t)(gateBase + gdir*(kn + u)) * 16));
            tag_n  = __ldg(tp + goldBase + kn + j);
            mskg_n = __ldg(mp + goldBase + kn + j);
            gate_n = __ldg(mp + gateBase + gdir*(kn + j));
        }

        // growth factors (off critical path)
        #pragma unroll
        for (int u = 0; u < 16; u++)
            gpk_c[u] = bf2u(__floats2bfloat162_rn(ex2f_(em_c[u].x * L2E),
                                                  ex2f_(em_c[u].y * L2E)));

        // ---- gold path: lane-local, one timestep per lane ----
        {
            const int t  = goldBase + k0 + j;
            const int tg = tag_c;
            int tgp = __shfl_up_sync(FULL, tag_c, 1, 16);
            const int l15 = __shfl_sync(FULL, tag_c, 15, 16);
            if (j == 0) tgp = carry_tag;
            carry_tag = l15;
            const float emg = __ldg(emb + (size_t)t*16 + tg);
            if (t == 0) {
                gold += s_start[tg] + emg;                 // ungated, matches ref
                if (mskg_c) packlm = tg;
            } else if (mskg_c) {
                gold += emg + s_trans[tg*16 + tgp];
                packlm = (t << 4) | tg;
            }
        }

        if (nb == 0) {
            // forward init: p0 = exp(start+em0), normalized to lane0; em0 folded -> gpk[0]=ONE
            float sA = (s_start[c0]   + em_c[0].x) * L2E;
            float sB = (s_start[c0+1] + em_c[0].y) * L2E;
            float m0 = __shfl_sync(FULL, sA, 0, 16);
            unsigned pf = bf2u(__floats2bfloat162_rn(ex2f_(sA - m0), ex2f_(sB - m0)));
            // backward init: beta_1023 = exp(end)
            unsigned pb = bf2u(__floats2bfloat162_rn(ex2f_(__ldg(end_t + c0)   * L2E),
                                                     ex2f_(__ldg(end_t + c0+1) * L2E)));
            pku  = isBwd ? pb : pf;
            off2 = isBwd ? 0.0f : m0;
            if (!isBwd) {
                gpk_c[0] = ONEBF;            // em_0 already in p0
                if (j == 0) gate_c = 1;      // t=0 init is ungated in reference
            }
        }

        const unsigned bal = __ballot_sync(FULL, gate_c != 0);
        if (bal == FULL) {
            STEP_F(0);  STEP_F(1);  STEP_F(2);  STEP_F(3);
            STEP_F(4);  STEP_F(5);  STEP_F(6);  STEP_F(7);
            STEP_F(8);  STEP_F(9);  STEP_F(10); STEP_F(11);
            STEP_F(12); STEP_F(13); STEP_F(14); STEP_F(15);
        } else {
            STEP_S(0);  STEP_S(1);  STEP_S(2);  STEP_S(3);
            STEP_S(4);  STEP_S(5);  STEP_S(6);  STEP_S(7);
            STEP_S(8);  STEP_S(9);  STEP_S(10); STEP_S(11);
            STEP_S(12); STEP_S(13); STEP_S(14); STEP_S(15);
        }
    }

    // ---- epilogue: Z = sum_s p_511(s) * beta_511(s) ----
    // fwd final = ptrk (= f_511 (.) q_511 = p_511); bwd final = pku (= beta_511)
    unsigned fin  = isBwd ? pku : ptrk;
    unsigned oth  = __shfl_sync(FULL, fin,  j + 16, 32);   // fwd lanes pull bwd half
    float    offO = __shfl_sync(FULL, off2, j + 16, 32);

    float z = 0.0f;
    if (!isBwd && ((j & 1) == 0))
        z = bflo_f(fin)*bflo_f(oth) + bfhi_f(fin)*bfhi_f(oth);
    z += __shfl_xor_sync(FULL, z, 8, 16);
    z += __shfl_xor_sync(FULL, z, 4, 16);
    z += __shfl_xor_sync(FULL, z, 2, 16);
    z += __shfl_xor_sync(FULL, z, 1, 16);

    gold += __shfl_xor_sync(FULL, gold, 16);
    gold += __shfl_xor_sync(FULL, gold, 8);
    gold += __shfl_xor_sync(FULL, gold, 4);
    gold += __shfl_xor_sync(FULL, gold, 2);
    gold += __shfl_xor_sync(FULL, gold, 1);

    packlm = max(packlm, __shfl_xor_sync(FULL, packlm, 16));
    packlm = max(packlm, __shfl_xor_sync(FULL, packlm, 8));
    packlm = max(packlm, __shfl_xor_sync(FULL, packlm, 4));
    packlm = max(packlm, __shfl_xor_sync(FULL, packlm, 2));
    packlm = max(packlm, __shfl_xor_sync(FULL, packlm, 1));

    if (tid == 0) {
        const int ltf = packlm & 15;
        const float logZ = (off2 + offO + lg2f_(z)) * LN2;
        g_nll[b] = logZ - (gold + __ldg(end_t + ltf));
    }
}

__global__ void crf_reduce_kernel(float* __restrict__ out)
{
    __shared__ float sm[256];
    int tid = threadIdx.x;
    float v = g_nll[tid] + g_nll[tid + 256] + g_nll[tid + 512] + g_nll[tid + 768];
    sm[tid] = v;
    __syncthreads();
    #pragma unroll
    for (int s = 128; s > 0; s >>= 1) {
        if (tid < s) sm[tid] += sm[tid + s];
        __syncthreads();
    }
    if (tid == 0) out[0] = sm[0] * (1.0f / 1024.0f);
}

extern "C" void kernel_launch(void* const* d_in, const int* in_sizes, int n_in,
                              void* d_out, int out_size)
{
    const float* emissions = (const float*)d_in[0];
    const int*   tags      = (const int*)d_in[1];
    const int*   mask      = (const int*)d_in[2];
    const float* trans     = (const float*)d_in[3];
    const float* start_t   = (const float*)d_in[4];
    const float* end_t     = (const float*)d_in[5];
    float* out = (float*)d_out;

    crf_forward_kernel<<<1024, 32>>>(emissions, tags, mask, trans, start_t, end_t);
    crf_reduce_kernel<<<1, 256>>>(out);
}

// round 6
// speedup vs baseline: 1.5178x; 1.1404x over previous
#include <cuda_runtime.h>
#include <cuda_bf16.h>

#define FULL 0xffffffffu
#define L2E  1.4426950408889634f
#define LN2  0.6931471805599453f
#define CRF_S 1024
#define CRF_T 16
#define ONEBF 0x3F803F80u

static __device__ __forceinline__ float ex2f_(float x){ float y; asm("ex2.approx.ftz.f32 %0,%1;" :"=f"(y):"f"(x)); return y; }
static __device__ __forceinline__ float lg2f_(float x){ float y; asm("lg2.approx.ftz.f32 %0,%1;" :"=f"(y):"f"(x)); return y; }
static __device__ __forceinline__ unsigned dup_lo(unsigned u){ unsigned r; asm("prmt.b32 %0,%1,%1,0x1010;" : "=r"(r):"r"(u)); return r; }
static __device__ __forceinline__ unsigned dup_hi(unsigned u){ unsigned r; asm("prmt.b32 %0,%1,%1,0x3232;" : "=r"(r):"r"(u)); return r; }

union UBF { unsigned u; __nv_bfloat162 b; float f; };
static __device__ __forceinline__ unsigned bf2u(__nv_bfloat162 v){ UBF c; c.b = v; return c.u; }
static __device__ __forceinline__ __nv_bfloat162 u2bf(unsigned u){ UBF c; c.u = u; return c.b; }
static __device__ __forceinline__ float bflo_f(unsigned u){ UBF c; c.u = u << 16; return c.f; }
static __device__ __forceinline__ float bfhi_f(unsigned u){ UBF c; c.u = u & 0xffff0000u; return c.f; }

__device__ float g_nll[1024];

// gather + 16x2 FMA tree within an 8-lane group; lane k holds packed (v_2k, v_2k+1)
#define GATHER_TREE \
    unsigned s0=__shfl_sync(FULL,v_,0,8), s1=__shfl_sync(FULL,v_,1,8), \
             s2=__shfl_sync(FULL,v_,2,8), s3=__shfl_sync(FULL,v_,3,8), \
             s4=__shfl_sync(FULL,v_,4,8), s5=__shfl_sync(FULL,v_,5,8), \
             s6=__shfl_sync(FULL,v_,6,8), s7=__shfl_sync(FULL,v_,7,8); \
    __nv_bfloat162 A_ = __hmul2(u2bf(dup_lo(s0)), Ep[0]); \
    __nv_bfloat162 B_ = __hmul2(u2bf(dup_hi(s0)), Ep[1]); \
    __nv_bfloat162 C_ = __hmul2(u2bf(dup_lo(s1)), Ep[2]); \
    __nv_bfloat162 D_ = __hmul2(u2bf(dup_hi(s1)), Ep[3]); \
    A_ = __hfma2(u2bf(dup_lo(s2)), Ep[ 4], A_); \
    B_ = __hfma2(u2bf(dup_hi(s2)), Ep[ 5], B_); \
    C_ = __hfma2(u2bf(dup_lo(s3)), Ep[ 6], C_); \
    D_ = __hfma2(u2bf(dup_hi(s3)), Ep[ 7], D_); \
    A_ = __hfma2(u2bf(dup_lo(s4)), Ep[ 8], A_); \
    B_ = __hfma2(u2bf(dup_hi(s4)), Ep[ 9], B_); \
    C_ = __hfma2(u2bf(dup_lo(s5)), Ep[10], C_); \
    D_ = __hfma2(u2bf(dup_hi(s5)), Ep[11], D_); \
    A_ = __hfma2(u2bf(dup_lo(s6)), Ep[12], A_); \
    B_ = __hfma2(u2bf(dup_hi(s6)), Ep[13], B_); \
    C_ = __hfma2(u2bf(dup_lo(s7)), Ep[14], C_); \
    D_ = __hfma2(u2bf(dup_hi(s7)), Ep[15], D_); \
    A_ = __hadd2(A_, B_); C_ = __hadd2(C_, D_); A_ = __hadd2(A_, C_);

// integer renorm: power-of-2 scale so group-lane-0 low-half ~ 1.0 (exact in bf16)
#define RENORM do { \
    unsigned u0_ = __shfl_sync(FULL, pku, 0, 8); \
    int Eb_ = (int)((u0_ >> 7) & 0xffu); \
    unsigned h_ = ((unsigned)(254 - Eb_)) << 7; \
    unsigned scl_ = h_ | (h_ << 16); \
    pku  = bf2u(__hmul2(u2bf(pku),  u2bf(scl_))); \
    ptrk = bf2u(__hmul2(u2bf(ptrk), u2bf(scl_))); \
    off2 += (float)(Eb_ - 127); \
} while (0)

#define STEP_F(K) do { \
    unsigned v_ = bf2u(__hmul2(u2bf(pku), u2bf(gpk_c[(K)]))); \
    GATHER_TREE; \
    ptrk = v_; pku = bf2u(A_); \
    if (((K)&7)==7) RENORM; } while (0)

#define STEP_S(K, GREG, GK) do { \
    unsigned v_ = bf2u(__hmul2(u2bf(pku), u2bf(gpk_c[(K)]))); \
    int g_ = __shfl_sync(FULL, (GREG), (GK), 8); \
    GATHER_TREE; \
    if (g_) { ptrk = v_; pku = bf2u(A_); } \
    if (((K)&7)==7) RENORM; } while (0)

__global__ void __launch_bounds__(32, 1)
crf_forward_kernel(const float* __restrict__ em,
                   const int* __restrict__ tags,
                   const int* __restrict__ mask,
                   const float* __restrict__ trans,
                   const float* __restrict__ start_t,
                   const float* __restrict__ end_t)
{
    __shared__ float s_trans[256];
    __shared__ float s_start[16];
    int tid = threadIdx.x;
    for (int i = tid; i < 256; i += 32) s_trans[i] = trans[i];
    if (tid < 16) s_start[tid] = start_t[tid];
    __syncwarp();

    const int  j8    = tid & 7;            // lane within 8-lane group
    const int  g     = tid >> 3;           // group 0..3
    const bool isBwd = (g & 1);
    const int  b     = blockIdx.x * 2 + (g >> 1);
    const int  c0    = j8 * 2;             // owned/dest state pair

    const float* emb = em   + (size_t)b * CRF_S * CRF_T;
    const int*   tp  = tags + (size_t)b * CRF_S;
    const int*   mp  = mask + (size_t)b * CRF_S;

    // fwd: Ep[i] = (E[i][c0], E[i][c0+1]);  bwd: Ep[i] = (E[c0][i], E[c0+1][i])
    __nv_bfloat162 Ep[16];
    #pragma unroll
    for (int i = 0; i < 16; i++) {
        int iA = isBwd ? (c0*16 + i)     : (i*16 + c0);
        int iB = isBwd ? ((c0+1)*16 + i) : (i*16 + c0 + 1);
        Ep[i] = __floats2bfloat162_rn(ex2f_(__ldg(trans + iA) * L2E),
                                      ex2f_(__ldg(trans + iB) * L2E));
    }

    const int gateBase = isBwd ? 1023 : 0;     // emission/gate stream
    const int gdir     = isBwd ? -1   : 1;
    const int goldBase = isBwd ? 512  : 0;     // gold stream (ascending)
    const float* emL   = emb + c0;

    // prefetch block 0 (16 stream positions)
    float2 em_n[16];
    #pragma unroll
    for (int u = 0; u < 16; u++)
        em_n[u] = __ldg((const float2*)(emL + (size_t)(gateBase + gdir*u) * 16));
    int tagA_n  = __ldg(tp + goldBase + j8);
    int tagB_n  = __ldg(tp + goldBase + 8 + j8);
    int mskA_n  = __ldg(mp + goldBase + j8);
    int mskB_n  = __ldg(mp + goldBase + 8 + j8);
    int gate0_n = __ldg(mp + gateBase + gdir*j8);
    int gate1_n = __ldg(mp + gateBase + gdir*(8 + j8));

    float2 em_c[16];
    unsigned gpk_c[16];
    int tagA_c, tagB_c, mskA_c, mskB_c, gate0_c, gate1_c;

    unsigned pku = 0, ptrk = ONEBF;
    float off2 = 0.0f, gold = 0.0f;
    int carry_tag = isBwd ? __ldg(tp + 511) : 0;
    int packlm = -2147483647;
    const unsigned gmask = 0xffu << (g * 8);

    for (int nb = 0; nb < 32; nb++) {
        const int k0 = nb * 16;
        #pragma unroll
        for (int u = 0; u < 16; u++) em_c[u] = em_n[u];
        tagA_c = tagA_n; tagB_c = tagB_n;
        mskA_c = mskA_n; mskB_c = mskB_n;
        gate0_c = gate0_n; gate1_c = gate1_n;

        if (nb < 31) {
            const int kn = k0 + 16;
            #pragma unroll
            for (int u = 0; u < 16; u++)
                em_n[u] = __ldg((const float2*)(emL + (size_t)(gateBase + gdir*(kn + u)) * 16));
            tagA_n  = __ldg(tp + goldBase + kn + j8);
            tagB_n  = __ldg(tp + goldBase + kn + 8 + j8);
            mskA_n  = __ldg(mp + goldBase + kn + j8);
            mskB_n  = __ldg(mp + goldBase + kn + 8 + j8);
            gate0_n = __ldg(mp + gateBase + gdir*(kn + j8));
            gate1_n = __ldg(mp + gateBase + gdir*(kn + 8 + j8));
        }

        // growth factors (off critical path)
        #pragma unroll
        for (int u = 0; u < 16; u++)
            gpk_c[u] = bf2u(__floats2bfloat162_rn(ex2f_(em_c[u].x * L2E),
                                                  ex2f_(em_c[u].y * L2E)));

        // ---- gold path: 2 timesteps per lane per block ----
        {
            // sub-round A: t = goldBase + k0 + j8
            int t  = goldBase + k0 + j8;
            int tg = tagA_c;
            int tgp = __shfl_up_sync(FULL, tagA_c, 1, 8);
            int l7  = __shfl_sync(FULL, tagA_c, 7, 8);
            if (j8 == 0) tgp = carry_tag;
            carry_tag = l7;
            float emg = __ldg(emb + (size_t)t*16 + tg);
            if (t == 0) {
                gold += s_start[tg] + emg;
                if (mskA_c) packlm = tg;
            } else if (mskA_c) {
                gold += emg + s_trans[tg*16 + tgp];
                packlm = (t << 4) | tg;
            }
            // sub-round B: t = goldBase + k0 + 8 + j8
            t  = goldBase + k0 + 8 + j8;
            tg = tagB_c;
            tgp = __shfl_up_sync(FULL, tagB_c, 1, 8);
            l7  = __shfl_sync(FULL, tagB_c, 7, 8);
            if (j8 == 0) tgp = carry_tag;
            carry_tag = l7;
            emg = __ldg(emb + (size_t)t*16 + tg);
            if (mskB_c) {
                gold += emg + s_trans[tg*16 + tgp];
                packlm = (t << 4) | tg;
            }
        }

        if (nb == 0) {
            // fwd init: p0 = exp(start + em0) normalized to state 0 (em0 folded -> gpk[0]=ONE)
            float sA = (s_start[c0]   + em_c[0].x) * L2E;
            float sB = (s_start[c0+1] + em_c[0].y) * L2E;
            float m0 = __shfl_sync(FULL, sA, 0, 8);
            unsigned pf = bf2u(__floats2bfloat162_rn(ex2f_(sA - m0), ex2f_(sB - m0)));
            // bwd init: beta_1023 = exp(end)
            unsigned pb = bf2u(__floats2bfloat162_rn(ex2f_(__ldg(end_t + c0)   * L2E),
                                                     ex2f_(__ldg(end_t + c0+1) * L2E)));
            pku  = isBwd ? pb : pf;
            off2 = isBwd ? 0.0f : m0;
            if (!isBwd) {
                gpk_c[0] = ONEBF;               // em_0 already in p0
                if (j8 == 0) gate0_c = 1;       // t=0 init ungated per reference
            }
        }

        const unsigned bal = __ballot_sync(FULL, (gate0_c != 0) && (gate1_c != 0));
        if ((bal & gmask) == gmask) {
            STEP_F(0);  STEP_F(1);  STEP_F(2);  STEP_F(3);
            STEP_F(4);  STEP_F(5);  STEP_F(6);  STEP_F(7);
            STEP_F(8);  STEP_F(9);  STEP_F(10); STEP_F(11);
            STEP_F(12); STEP_F(13); STEP_F(14); STEP_F(15);
        } else {
            STEP_S(0,  gate0_c, 0); STEP_S(1,  gate0_c, 1);
            STEP_S(2,  gate0_c, 2); STEP_S(3,  gate0_c, 3);
            STEP_S(4,  gate0_c, 4); STEP_S(5,  gate0_c, 5);
            STEP_S(6,  gate0_c, 6); STEP_S(7,  gate0_c, 7);
            STEP_S(8,  gate1_c, 0); STEP_S(9,  gate1_c, 1);
            STEP_S(10, gate1_c, 2); STEP_S(11, gate1_c, 3);
            STEP_S(12, gate1_c, 4); STEP_S(13, gate1_c, 5);
            STEP_S(14, gate1_c, 6); STEP_S(15, gate1_c, 7);
        }
    }

    // ---- epilogue: Z = sum_s alpha_511(s) * beta_511(s) ----
    unsigned fin  = isBwd ? pku : ptrk;                 // fwd: ptrk=alpha_511; bwd: pku=beta_511
    unsigned oth  = __shfl_sync(FULL, fin,  (tid + 8) & 31, 32);
    float    offO = __shfl_sync(FULL, off2, (tid + 8) & 31, 32);

    float z = 0.0f;
    if (!isBwd)
        z = bflo_f(fin)*bflo_f(oth) + bfhi_f(fin)*bfhi_f(oth);
    z += __shfl_xor_sync(FULL, z, 4, 8);
    z += __shfl_xor_sync(FULL, z, 2, 8);
    z += __shfl_xor_sync(FULL, z, 1, 8);

    gold += __shfl_xor_sync(FULL, gold, 4, 8);
    gold += __shfl_xor_sync(FULL, gold, 2, 8);
    gold += __shfl_xor_sync(FULL, gold, 1, 8);
    float goldO = __shfl_sync(FULL, gold, (tid + 8) & 31, 32);

    packlm = max(packlm, __shfl_xor_sync(FULL, packlm, 4, 8));
    packlm = max(packlm, __shfl_xor_sync(FULL, packlm, 2, 8));
    packlm = max(packlm, __shfl_xor_sync(FULL, packlm, 1, 8));
    int pmO = __shfl_sync(FULL, packlm, (tid + 8) & 31, 32);

    if ((tid & 15) == 0) {  // tid 0 -> batch b, tid 16 -> batch b (other pair)
        const int pm  = max(packlm, pmO);
        const int ltf = pm & 15;
        const float logZ = (off2 + offO + lg2f_(z)) * LN2;
        g_nll[b] = logZ - (gold + goldO + __ldg(end_t + ltf));
    }
}

__global__ void crf_reduce_kernel(float* __restrict__ out)
{
    __shared__ float sm[256];
    int tid = threadIdx.x;
    float v = g_nll[tid] + g_nll[tid + 256] + g_nll[tid + 512] + g_nll[tid + 768];
    sm[tid] = v;
    __syncthreads();
    #pragma unroll
    for (int s = 128; s > 0; s >>= 1) {
        if (tid < s) sm[tid] += sm[tid + s];
        __syncthreads();
    }
    if (tid == 0) out[0] = sm[0] * (1.0f / 1024.0f);
}

extern "C" void kernel_launch(void* const* d_in, const int* in_sizes, int n_in,
                              void* d_out, int out_size)
{
    const float* emissions = (const float*)d_in[0];
    const int*   tags      = (const int*)d_in[1];
    const int*   mask      = (const int*)d_in[2];
    const float* trans     = (const float*)d_in[3];
    const float* start_t   = (const float*)d_in[4];
    const float* end_t     = (const float*)d_in[5];
    float* out = (float*)d_out;

    crf_forward_kernel<<<512, 32>>>(emissions, tags, mask, trans, start_t, end_t);
    crf_reduce_kernel<<<1, 256>>>(out);
}